// round 9
// baseline (speedup 1.0000x reference)
#include <cuda_runtime.h>
#include <math.h>
#include <stdint.h>

#define VOCAB 32000
#define EMB 256
#define HID 256
#define BATCH 64
#define SEQT 2048

// Scratch: V[v][j] = sum_e emb[v][e]*W_ih[e][j] + b_ih[j] + b_hh[j]  (32 MB, L2-resident)
__device__ float g_V[VOCAB * HID];

// ---------------------------------------------------------------------------
// f32x2 packed helpers (PTX-only; ptxas won't auto-fuse)
// ---------------------------------------------------------------------------
__device__ __forceinline__ unsigned long long pack2(float lo, float hi) {
    unsigned long long r;
    asm("mov.b64 %0, {%1, %2};" : "=l"(r) : "f"(lo), "f"(hi));
    return r;
}
__device__ __forceinline__ void fma2(unsigned long long& acc,
                                     unsigned long long a, unsigned long long b) {
    asm("fma.rn.f32x2 %0, %1, %2, %0;" : "+l"(acc) : "l"(a), "l"(b));
}
__device__ __forceinline__ unsigned long long add2(unsigned long long a,
                                                   unsigned long long b) {
    unsigned long long r;
    asm("add.rn.f32x2 %0, %1, %2;" : "=l"(r) : "l"(a), "l"(b));
    return r;
}
__device__ __forceinline__ void unpack2(unsigned long long v, float& lo, float& hi) {
    asm("mov.b64 {%0, %1}, %2;" : "=f"(lo), "=f"(hi) : "l"(v));
}
__device__ __forceinline__ unsigned long long shfl_bfly_u64(unsigned long long v,
                                                            int mask) {
    uint32_t lo = (uint32_t)v, hi = (uint32_t)(v >> 32);
    lo = __shfl_xor_sync(0xffffffffu, lo, mask);
    hi = __shfl_xor_sync(0xffffffffu, hi, mask);
    return ((unsigned long long)hi << 32) | lo;
}

// ---------------------------------------------------------------------------
// Kernel 1: vocab projection GEMM  [32000,256] x [256,256] + bias  (f32x2)
// ---------------------------------------------------------------------------
__global__ void __launch_bounds__(256) vocab_proj_kernel(
    const float* __restrict__ emb, const float* __restrict__ W_ih,
    const float* __restrict__ b_ih, const float* __restrict__ b_hh)
{
    __shared__ float As_T[32][68];
    const int row0 = blockIdx.x * 64;
    const int j = threadIdx.x;

    const float bias = b_ih[j] + b_hh[j];

    unsigned long long acc[32];
#pragma unroll
    for (int p = 0; p < 32; p++) acc[p] = 0ull;

#pragma unroll 1
    for (int k0 = 0; k0 < EMB; k0 += 32) {
        __syncthreads();
#pragma unroll
        for (int it = 0; it < 8; it++) {
            int idx = it * 256 + threadIdx.x;
            int r  = idx >> 5;
            int kk = idx & 31;
            As_T[kk][r] = emb[(size_t)(row0 + r) * EMB + (k0 + kk)];
        }
        __syncthreads();

        float wt[32];
#pragma unroll
        for (int kk = 0; kk < 32; kk++)
            wt[kk] = W_ih[(size_t)(k0 + kk) * HID + j];

#pragma unroll
        for (int kk = 0; kk < 32; kk++) {
            unsigned long long ws = pack2(wt[kk], wt[kk]);
#pragma unroll
            for (int rp2 = 0; rp2 < 16; rp2++) {
                ulonglong2 av = *(const ulonglong2*)&As_T[kk][4 * rp2];
                fma2(acc[2 * rp2 + 0], av.x, ws);
                fma2(acc[2 * rp2 + 1], av.y, ws);
            }
        }
    }

#pragma unroll
    for (int p = 0; p < 32; p++) {
        float lo, hi;
        unpack2(acc[p], lo, hi);
        g_V[(size_t)(row0 + 2 * p + 0) * HID + j] = lo + bias;
        g_V[(size_t)(row0 + 2 * p + 1) * HID + j] = hi + bias;
    }
}

// ---------------------------------------------------------------------------
// Kernel 2: recurrence, SINGLE CTA per chain, 512 threads (16 warps).
// Thread (warp w, lane l): kg = l&3 -> k in [64kg, 64kg+64), cl = l>>2.
// Owns 2 columns: c_i = 16w + 8i + cl (i=0,1); lanes kg<2 finalize c_kg.
// W: 48 k's/col in regs (48 f32x2/thread = 96 regs -> NO spills),
//    16 k's/col in per-thread SMEM scratch (64 KB/step crossbar, overlaps FMA).
// h: SMEM, 4 bank-staggered kg-groups; reduce across kg lanes via 2 bfly rounds.
// One __syncthreads per step.
// ---------------------------------------------------------------------------
#define KREGP 24   // k-pairs per column in registers (48 k's)
#define GSTR  68   // floats per h group (64 + 4 pad)
#define WSM_TH 36  // floats of W scratch per thread (32 used + 4 pad; 144B stride)

__global__ void __launch_bounds__(512, 1)
rnn_kernel(const int* __restrict__ source, const float* __restrict__ W_hh,
           float* __restrict__ out)
{
    extern __shared__ float sm[];
    float* Wsm  = sm;                               // 512*36 floats = 73728 B
    float* hbuf = sm + 512 * WSM_TH;                // 2 * 4*68 floats
    int*   srcs = (int*)(hbuf + 2 * 4 * GSTR);      // 2048 ints

    const int t  = threadIdx.x;
    const int w  = t >> 5;
    const int l  = t & 31;
    const int kg = l & 3;
    const int cl = l >> 2;
    const int b  = blockIdx.x;
    const int kb = kg * 64;                    // lane's k-range base
    const int c0 = 16 * w + cl;                // first owned column
    const int c1 = 16 * w + 8 + cl;            // second owned column
    const bool fin = (kg < 2);                 // lanes kg 0/1 finalize c_kg
    const int cown = fin ? (16 * w + 8 * kg + cl) : 0;

    for (int i = t; i < SEQT; i += 512) srcs[i] = source[b * SEQT + i];
    for (int i = t; i < 2 * 4 * GSTR; i += 512) hbuf[i] = 0.0f;

    // ---- Register-resident W: 2 cols x 24 k-pairs (k's [kb, kb+48))
    unsigned long long wr[2 * KREGP];
#pragma unroll
    for (int kk = 0; kk < KREGP; kk++) {
        wr[kk]         = pack2(W_hh[(size_t)(kb + 2 * kk + 0) * HID + c0],
                               W_hh[(size_t)(kb + 2 * kk + 1) * HID + c0]);
        wr[KREGP + kk] = pack2(W_hh[(size_t)(kb + 2 * kk + 0) * HID + c1],
                               W_hh[(size_t)(kb + 2 * kk + 1) * HID + c1]);
    }

    // ---- SMEM-resident W: 2 cols x 16 k's [kb+48, kb+64) per thread
    {
        float* wp = Wsm + t * WSM_TH;
#pragma unroll
        for (int m = 0; m < 16; m++) {
            wp[m]      = W_hh[(size_t)(kb + 48 + m) * HID + c0];
            wp[16 + m] = W_hh[(size_t)(kb + 48 + m) * HID + c1];
        }
    }

    __syncthreads();

    const ulonglong2* wv = (const ulonglong2*)(Wsm + t * WSM_TH);  // 8 u2: col0 q0-3, col1 q4-7

    // h read base per buffer for this lane's k-slice; write slot per buffer
    const float* hr0 = hbuf + kg * GSTR;
    const float* hr1 = hbuf + 4 * GSTR + kg * GSTR;
    float* hw0 = hbuf + 4 * GSTR + (cown >> 6) * GSTR + (cown & 63);  // write when cur=0
    float* hw1 = hbuf + (cown >> 6) * GSTR + (cown & 63);             // write when cur=1

    float hval = 0.0f;
    float xv = fin ? g_V[(size_t)srcs[0] * HID + cown] : 0.0f;

#pragma unroll 1
    for (int step = 0; step < SEQT; step++) {
        // Prefetch next step's x-projection (in flight across FMA + barrier)
        const int ns = (step + 1 < SEQT) ? step + 1 : step;
        const float xv_n = fin ? g_V[(size_t)srcs[ns] * HID + cown] : 0.0f;

        const float* hg = (step & 1) ? hr1 : hr0;

        unsigned long long a0 = 0, a1 = 0;

        // SMEM-W part first: issue the per-thread LDS early (fills LSU while
        // the register-W FMA block runs on the FMA port)
        {
            const ulonglong2* hsm = (const ulonglong2*)(hg + 48);  // k's [kb+48,kb+64)
#pragma unroll
            for (int q = 0; q < 4; q++) {
                ulonglong2 hh = hsm[q];
                ulonglong2 w0 = wv[q];
                ulonglong2 w1 = wv[4 + q];
                fma2(a0, hh.x, w0.x); fma2(a0, hh.y, w0.y);
                fma2(a1, hh.x, w1.x); fma2(a1, hh.y, w1.y);
            }
        }

        // Register-W part: k-pairs 0..23 of this lane's slice
        {
            const ulonglong2* hp2 = (const ulonglong2*)hg;
#pragma unroll
            for (int q = 0; q < 12; q++) {
                ulonglong2 hh = hp2[q];  // k-pairs 2q, 2q+1
                fma2(a0, hh.x, wr[2 * q]);         fma2(a0, hh.y, wr[2 * q + 1]);
                fma2(a1, hh.x, wr[KREGP + 2 * q]); fma2(a1, hh.y, wr[KREGP + 2 * q + 1]);
            }
        }

        // Pack per-column partials, reduce across the 4 kg-lanes
        float s0lo, s0hi, s1lo, s1hi;
        unpack2(a0, s0lo, s0hi);
        unpack2(a1, s1lo, s1hi);
        unsigned long long p01 = pack2(s0lo + s0hi, s1lo + s1hi);

        p01 = add2(p01, shfl_bfly_u64(p01, 1));
        p01 = add2(p01, shfl_bfly_u64(p01, 2));

        if (fin) {
            float f0, f1;
            unpack2(p01, f0, f1);
            const float mine = (kg == 0) ? f0 : f1;
            const float pre = xv + mine;
            const float e = __expf(2.0f * pre);
            hval = 1.0f - __fdividef(2.0f, e + 1.0f);
            *((step & 1) ? hw1 : hw0) = hval;
        }

        __syncthreads();
        xv = xv_n;
    }

    if (fin) out[b * HID + cown] = hval;
}

// ---------------------------------------------------------------------------
extern "C" void kernel_launch(void* const* d_in, const int* in_sizes, int n_in,
                              void* d_out, int out_size)
{
    const int*   source    = (const int*)d_in[0];
    const float* embedding = (const float*)d_in[1];
    const float* W_ih      = (const float*)d_in[2];
    const float* W_hh      = (const float*)d_in[3];
    const float* b_ih      = (const float*)d_in[4];
    const float* b_hh      = (const float*)d_in[5];
    float* out = (float*)d_out;

    const int smem_bytes = (512 * WSM_TH + 2 * 4 * GSTR) * 4 + SEQT * 4;  // ~84 KB
    cudaFuncSetAttribute(rnn_kernel,
                         cudaFuncAttributeMaxDynamicSharedMemorySize,
                         smem_bytes);

    vocab_proj_kernel<<<VOCAB / 64, 256>>>(embedding, W_ih, b_ih, b_hh);
    rnn_kernel<<<BATCH, 512, smem_bytes>>>(source, W_hh, out);
}

// round 10
// speedup vs baseline: 1.0988x; 1.0988x over previous
#include <cuda_runtime.h>
#include <math.h>
#include <stdint.h>

#define VOCAB 32000
#define EMB 256
#define HID 256
#define BATCH 64
#define SEQT 2048

// Scratch: V[v][j] = sum_e emb[v][e]*W_ih[e][j] + b_ih[j] + b_hh[j]  (32 MB, L2-resident)
__device__ float g_V[VOCAB * HID];

// ---------------------------------------------------------------------------
// f32x2 packed helpers (PTX-only; ptxas won't auto-fuse)
// ---------------------------------------------------------------------------
__device__ __forceinline__ unsigned long long pack2(float lo, float hi) {
    unsigned long long r;
    asm("mov.b64 %0, {%1, %2};" : "=l"(r) : "f"(lo), "f"(hi));
    return r;
}
__device__ __forceinline__ void fma2(unsigned long long& acc,
                                     unsigned long long a, unsigned long long b) {
    asm("fma.rn.f32x2 %0, %1, %2, %0;" : "+l"(acc) : "l"(a), "l"(b));
}
__device__ __forceinline__ unsigned long long add2(unsigned long long a,
                                                   unsigned long long b) {
    unsigned long long r;
    asm("add.rn.f32x2 %0, %1, %2;" : "=l"(r) : "l"(a), "l"(b));
    return r;
}
__device__ __forceinline__ void unpack2(unsigned long long v, float& lo, float& hi) {
    asm("mov.b64 {%0, %1}, %2;" : "=f"(lo), "=f"(hi) : "l"(v));
}

// Cluster / mbarrier helpers
__device__ __forceinline__ uint32_t smem_u32(const void* p) {
    uint32_t a;
    asm("{ .reg .u64 t; cvta.to.shared.u64 t, %1; cvt.u32.u64 %0, t; }"
        : "=r"(a) : "l"(p));
    return a;
}
__device__ __forceinline__ uint32_t mapa_peer(uint32_t addr, uint32_t rank) {
    uint32_t r;
    asm("mapa.shared::cluster.u32 %0, %1, %2;" : "=r"(r) : "r"(addr), "r"(rank));
    return r;
}
__device__ __forceinline__ void mbar_init(uint32_t addr, uint32_t count) {
    asm volatile("mbarrier.init.shared.b64 [%0], %1;" :: "r"(addr), "r"(count) : "memory");
}
__device__ __forceinline__ void mbar_expect_tx(uint32_t addr, uint32_t bytes) {
    asm volatile("mbarrier.arrive.expect_tx.shared.b64 _, [%0], %1;"
                 :: "r"(addr), "r"(bytes) : "memory");
}
// Remote store fused with peer-mbar tx completion (data + signal in one op)
__device__ __forceinline__ void st_async_f32(uint32_t remote_addr, float v,
                                             uint32_t remote_mbar) {
    asm volatile(
        "st.async.shared::cluster.mbarrier::complete_tx::bytes.b32 [%0], %1, [%2];"
        :: "r"(remote_addr), "r"(__float_as_int(v)), "r"(remote_mbar) : "memory");
}
__device__ __forceinline__ void mbar_wait_parity(uint32_t addr, uint32_t parity) {
    uint32_t done;
    asm volatile(
        "{\n\t"
        ".reg .pred p;\n\t"
        "mbarrier.try_wait.parity.acquire.cluster.shared::cta.b64 p, [%1], %2;\n\t"
        "selp.b32 %0, 1, 0, p;\n\t"
        "}" : "=r"(done) : "r"(addr), "r"(parity) : "memory");
    if (!done) {
        asm volatile(
            "{\n\t"
            ".reg .pred P1;\n\t"
            "WL_%=:\n\t"
            "mbarrier.try_wait.parity.acquire.cluster.shared::cta.b64 P1, [%0], %1, 0x989680;\n\t"
            "@P1 bra.uni WD_%=;\n\t"
            "bra.uni WL_%=;\n\t"
            "WD_%=:\n\t"
            "}" :: "r"(addr), "r"(parity) : "memory");
    }
}
#define CLUSTER_SYNC() do { \
    asm volatile("barrier.cluster.arrive.aligned;" ::: "memory"); \
    asm volatile("barrier.cluster.wait.aligned;" ::: "memory"); \
} while (0)

// ---------------------------------------------------------------------------
// Kernel 1: vocab projection GEMM  [32000,256] x [256,256] + bias  (f32x2)
// ---------------------------------------------------------------------------
__global__ void __launch_bounds__(256) vocab_proj_kernel(
    const float* __restrict__ emb, const float* __restrict__ W_ih,
    const float* __restrict__ b_ih, const float* __restrict__ b_hh)
{
    __shared__ float As_T[32][68];
    const int row0 = blockIdx.x * 64;
    const int j = threadIdx.x;

    const float bias = b_ih[j] + b_hh[j];

    unsigned long long acc[32];
#pragma unroll
    for (int p = 0; p < 32; p++) acc[p] = 0ull;

#pragma unroll 1
    for (int k0 = 0; k0 < EMB; k0 += 32) {
        __syncthreads();
#pragma unroll
        for (int it = 0; it < 8; it++) {
            int idx = it * 256 + threadIdx.x;
            int r  = idx >> 5;
            int kk = idx & 31;
            As_T[kk][r] = emb[(size_t)(row0 + r) * EMB + (k0 + kk)];
        }
        __syncthreads();

        float wt[32];
#pragma unroll
        for (int kk = 0; kk < 32; kk++)
            wt[kk] = W_ih[(size_t)(k0 + kk) * HID + j];

#pragma unroll
        for (int kk = 0; kk < 32; kk++) {
            unsigned long long ws = pack2(wt[kk], wt[kk]);
#pragma unroll
            for (int rp2 = 0; rp2 < 16; rp2++) {
                ulonglong2 av = *(const ulonglong2*)&As_T[kk][4 * rp2];
                fma2(acc[2 * rp2 + 0], av.x, ws);
                fma2(acc[2 * rp2 + 1], av.y, ws);
            }
        }
    }

#pragma unroll
    for (int p = 0; p < 32; p++) {
        float lo, hi;
        unpack2(acc[p], lo, hi);
        g_V[(size_t)(row0 + 2 * p + 0) * HID + j] = lo + bias;
        g_V[(size_t)(row0 + 2 * p + 1) * HID + j] = hi + bias;
    }
}

// ---------------------------------------------------------------------------
// Kernel 2: recurrence, TWO chains per 2-CTA cluster (32 clusters, 64 CTAs).
// W_hh is shared across chains -> one register-resident W slice (64 f32x2)
// serves both. Per step, phases A and B are interleaved: chain A's DSMEM
// h-transit hides under chain B's full FMA+tail phase, and vice versa.
// Per phase (R4 structure): remote warps wait mbar -> all warps FMA (local
// warps read own-half h, remote warps read peer-half delivered by st.async)
// -> t>=128 STS partial -> bar -> t<128 finalize (tanh), store h local +
// st.async h to peer (data+signal fused).
// ---------------------------------------------------------------------------
__global__ void __launch_bounds__(256, 1) __cluster_dims__(2, 1, 1)
rnn_kernel(const int* __restrict__ source, const float* __restrict__ W_hh,
           float* __restrict__ out)
{
    __shared__ float hsA[2][256], hsB[2][256];
    __shared__ float pA[128], pB[128];
    __shared__ int   srcsA[SEQT], srcsB[SEQT];
    __shared__ __align__(8) unsigned long long mbA[2], mbB[2];

    const int t   = threadIdx.x;
    const int col = t & 127;
    const int kh  = t >> 7;
    const int k0  = kh * 128;
    const int cid = blockIdx.x >> 1;
    const int bA  = 2 * cid;
    const int bB  = 2 * cid + 1;

    uint32_t rank;
    asm("mov.u32 %0, %%cluster_ctarank;" : "=r"(rank));

    const int  jout      = (int)rank * 128 + col;  // this CTA's column for t<128
    const bool is_remote = (kh != (int)rank);      // warp-uniform

    for (int i = t; i < SEQT; i += 256) {
        srcsA[i] = source[bA * SEQT + i];
        srcsB[i] = source[bB * SEQT + i];
    }

    // W_hh[k0..k0+127][jout] register-resident as 64 f32x2 (shared by A and B)
    unsigned long long wreg[64];
#pragma unroll
    for (int i = 0; i < 64; i++)
        wreg[i] = pack2(W_hh[(size_t)(k0 + 2 * i + 0) * HID + jout],
                        W_hh[(size_t)(k0 + 2 * i + 1) * HID + jout]);

    hsA[0][t] = 0.0f; hsA[1][t] = 0.0f;
    hsB[0][t] = 0.0f; hsB[1][t] = 0.0f;
    if (t == 0) {
#pragma unroll
        for (int q = 0; q < 2; q++) {
            mbar_init(smem_u32(&mbA[q]), 1);
            mbar_init(smem_u32(&mbB[q]), 1);
            mbar_expect_tx(smem_u32(&mbA[q]), 512);  // pre-arm phase 0
            mbar_expect_tx(smem_u32(&mbB[q]), 512);
        }
    }

    // Peer addresses (used by finalizer threads t<128 for their jout slot)
    uint32_t phA[2], phB[2], pmbA[2], pmbB[2], mbA_l[2], mbB_l[2];
#pragma unroll
    for (int q = 0; q < 2; q++) {
        phA[q]   = mapa_peer(smem_u32(&hsA[q][jout]), rank ^ 1u);
        phB[q]   = mapa_peer(smem_u32(&hsB[q][jout]), rank ^ 1u);
        pmbA[q]  = mapa_peer(smem_u32(&mbA[q]), rank ^ 1u);
        pmbB[q]  = mapa_peer(smem_u32(&mbB[q]), rank ^ 1u);
        mbA_l[q] = smem_u32(&mbA[q]);
        mbB_l[q] = smem_u32(&mbB[q]);
    }

    __syncthreads();
    CLUSTER_SYNC();  // mbar init + expect_tx + zeroed hs visible cluster-wide

    float hA = 0.0f, hB = 0.0f;

    // One phase of one chain; returns updated hval for finalizers.
    auto phase = [&](float (&hs)[2][256], float* part,
                     const uint32_t* mbl, const uint32_t* pmb,
                     const uint32_t* ph, const int* srcs,
                     float& hv, int step) {
        const int cur = step & 1;
        const int nxt = cur ^ 1;

        // Finalizers prefetch x-projection (L2 gather; consumed at tail)
        float xv = 0.0f;
        if (t < 128) xv = g_V[(size_t)srcs[step] * HID + jout];

        // Remote warps wait for peer's h (sent one step ago; transit hidden
        // under the other chain's phase). Re-arm by one remote thread.
        if (is_remote && step > 0) {
            mbar_wait_parity(mbl[cur], ((uint32_t)(step - 1) >> 1) & 1u);
            if (col == 0 && (t & 31) == 0) mbar_expect_tx(mbl[cur], 512);
        }

        const float* hp = &hs[cur][k0];
        unsigned long long a0 = 0, a1 = 0, a2 = 0, a3 = 0;
        unsigned long long b0 = 0, b1 = 0, b2 = 0, b3 = 0;
#pragma unroll
        for (int q = 0; q < 32; q += 4) {
            ulonglong2 h0 = *(const ulonglong2*)(hp + 4 * (q + 0));
            ulonglong2 h1 = *(const ulonglong2*)(hp + 4 * (q + 1));
            ulonglong2 h2 = *(const ulonglong2*)(hp + 4 * (q + 2));
            ulonglong2 h3 = *(const ulonglong2*)(hp + 4 * (q + 3));
            fma2(a0, h0.x, wreg[2 * q + 0]); fma2(b0, h0.y, wreg[2 * q + 1]);
            fma2(a1, h1.x, wreg[2 * q + 2]); fma2(b1, h1.y, wreg[2 * q + 3]);
            fma2(a2, h2.x, wreg[2 * q + 4]); fma2(b2, h2.y, wreg[2 * q + 5]);
            fma2(a3, h3.x, wreg[2 * q + 6]); fma2(b3, h3.y, wreg[2 * q + 7]);
        }
        unsigned long long s = add2(add2(add2(a0, a1), add2(a2, a3)),
                                    add2(add2(b0, b1), add2(b2, b3)));
        float lo, hi;
        unpack2(s, lo, hi);
        const float pr = lo + hi;

        if (t >= 128) part[col] = pr;
        __syncthreads();  // partials ready; also orders hs[cur] reads

        if (t < 128) {
            const float pre = xv + pr + part[col];
            const float e = __expf(2.0f * pre);
            hv = 1.0f - __fdividef(2.0f, e + 1.0f);
            hs[nxt][jout] = hv;                   // local copy
            st_async_f32(ph[nxt], hv, pmb[nxt]);  // peer copy + signal fused
        }
        // No second bar: next phase touches the OTHER chain's buffers; the
        // next use of this chain's data is gated by that phase's own bar.
    };

#pragma unroll 1
    for (int step = 0; step < SEQT; step++) {
        phase(hsA, pA, mbA_l, pmbA, phA, srcsA, hA, step);  // chain A
        phase(hsB, pB, mbB_l, pmbB, phB, srcsB, hB, step);  // chain B
    }

    if (t < 128) {
        out[bA * HID + jout] = hA;
        out[bB * HID + jout] = hB;
    }

    CLUSTER_SYNC();  // keep SMEM/mbar alive for in-flight final st.asyncs
}

// ---------------------------------------------------------------------------
extern "C" void kernel_launch(void* const* d_in, const int* in_sizes, int n_in,
                              void* d_out, int out_size)
{
    const int*   source    = (const int*)d_in[0];
    const float* embedding = (const float*)d_in[1];
    const float* W_ih      = (const float*)d_in[2];
    const float* W_hh      = (const float*)d_in[3];
    const float* b_ih      = (const float*)d_in[4];
    const float* b_hh      = (const float*)d_in[5];
    float* out = (float*)d_out;

    vocab_proj_kernel<<<VOCAB / 64, 256>>>(embedding, W_ih, b_ih, b_hh);
    rnn_kernel<<<BATCH, 256>>>(source, W_hh, out);  // 64 CTAs = 32 clusters x 2
}

// round 11
// speedup vs baseline: 1.7135x; 1.5594x over previous
#include <cuda_runtime.h>
#include <math.h>
#include <stdint.h>

#define VOCAB 32000
#define EMB 256
#define HID 256
#define BATCH 64
#define SEQT 2048

// Scratch: V[v][j] = sum_e emb[v][e]*W_ih[e][j] + b_ih[j] + b_hh[j]  (32 MB, L2-resident)
__device__ float g_V[VOCAB * HID];

// ---------------------------------------------------------------------------
// f32x2 packed helpers (PTX-only; ptxas won't auto-fuse)
// ---------------------------------------------------------------------------
__device__ __forceinline__ unsigned long long pack2(float lo, float hi) {
    unsigned long long r;
    asm("mov.b64 %0, {%1, %2};" : "=l"(r) : "f"(lo), "f"(hi));
    return r;
}
__device__ __forceinline__ void fma2(unsigned long long& acc,
                                     unsigned long long a, unsigned long long b) {
    asm("fma.rn.f32x2 %0, %1, %2, %0;" : "+l"(acc) : "l"(a), "l"(b));
}
__device__ __forceinline__ unsigned long long add2(unsigned long long a,
                                                   unsigned long long b) {
    unsigned long long r;
    asm("add.rn.f32x2 %0, %1, %2;" : "=l"(r) : "l"(a), "l"(b));
    return r;
}
__device__ __forceinline__ void unpack2(unsigned long long v, float& lo, float& hi) {
    asm("mov.b64 {%0, %1}, %2;" : "=f"(lo), "=f"(hi) : "l"(v));
}

// Cluster / mbarrier helpers
__device__ __forceinline__ uint32_t smem_u32(const void* p) {
    uint32_t a;
    asm("{ .reg .u64 t; cvta.to.shared.u64 t, %1; cvt.u32.u64 %0, t; }"
        : "=r"(a) : "l"(p));
    return a;
}
__device__ __forceinline__ uint32_t mapa_peer(uint32_t addr, uint32_t rank) {
    uint32_t r;
    asm("mapa.shared::cluster.u32 %0, %1, %2;" : "=r"(r) : "r"(addr), "r"(rank));
    return r;
}
__device__ __forceinline__ void mbar_init(uint32_t addr, uint32_t count) {
    asm volatile("mbarrier.init.shared.b64 [%0], %1;" :: "r"(addr), "r"(count) : "memory");
}
__device__ __forceinline__ void mbar_expect_tx(uint32_t addr, uint32_t bytes) {
    asm volatile("mbarrier.arrive.expect_tx.shared.b64 _, [%0], %1;"
                 :: "r"(addr), "r"(bytes) : "memory");
}
// Remote store fused with peer-mbar tx completion (data + signal in one op)
__device__ __forceinline__ void st_async_f32(uint32_t remote_addr, float v,
                                             uint32_t remote_mbar) {
    asm volatile(
        "st.async.shared::cluster.mbarrier::complete_tx::bytes.b32 [%0], %1, [%2];"
        :: "r"(remote_addr), "r"(__float_as_int(v)), "r"(remote_mbar) : "memory");
}
__device__ __forceinline__ void mbar_wait_parity(uint32_t addr, uint32_t parity) {
    uint32_t done;
    asm volatile(
        "{\n\t"
        ".reg .pred p;\n\t"
        "mbarrier.try_wait.parity.acquire.cluster.shared::cta.b64 p, [%1], %2;\n\t"
        "selp.b32 %0, 1, 0, p;\n\t"
        "}" : "=r"(done) : "r"(addr), "r"(parity) : "memory");
    if (!done) {
        asm volatile(
            "{\n\t"
            ".reg .pred P1;\n\t"
            "WL_%=:\n\t"
            "mbarrier.try_wait.parity.acquire.cluster.shared::cta.b64 P1, [%0], %1, 0x100;\n\t"
            "@P1 bra.uni WD_%=;\n\t"
            "bra.uni WL_%=;\n\t"
            "WD_%=:\n\t"
            "}" :: "r"(addr), "r"(parity) : "memory");
    }
}
#define CLUSTER_SYNC() do { \
    asm volatile("barrier.cluster.arrive.aligned;" ::: "memory"); \
    asm volatile("barrier.cluster.wait.aligned;" ::: "memory"); \
} while (0)

// ---------------------------------------------------------------------------
// Kernel 1: vocab projection GEMM  [32000,256] x [256,256] + bias  (f32x2)
// ---------------------------------------------------------------------------
__global__ void __launch_bounds__(256) vocab_proj_kernel(
    const float* __restrict__ emb, const float* __restrict__ W_ih,
    const float* __restrict__ b_ih, const float* __restrict__ b_hh)
{
    __shared__ float As_T[32][68];
    const int row0 = blockIdx.x * 64;
    const int j = threadIdx.x;

    const float bias = b_ih[j] + b_hh[j];

    unsigned long long acc[32];
#pragma unroll
    for (int p = 0; p < 32; p++) acc[p] = 0ull;

#pragma unroll 1
    for (int k0 = 0; k0 < EMB; k0 += 32) {
        __syncthreads();
#pragma unroll
        for (int it = 0; it < 8; it++) {
            int idx = it * 256 + threadIdx.x;
            int r  = idx >> 5;
            int kk = idx & 31;
            As_T[kk][r] = emb[(size_t)(row0 + r) * EMB + (k0 + kk)];
        }
        __syncthreads();

        float wt[32];
#pragma unroll
        for (int kk = 0; kk < 32; kk++)
            wt[kk] = W_ih[(size_t)(k0 + kk) * HID + j];

#pragma unroll
        for (int kk = 0; kk < 32; kk++) {
            unsigned long long ws = pack2(wt[kk], wt[kk]);
#pragma unroll
            for (int rp2 = 0; rp2 < 16; rp2++) {
                ulonglong2 av = *(const ulonglong2*)&As_T[kk][4 * rp2];
                fma2(acc[2 * rp2 + 0], av.x, ws);
                fma2(acc[2 * rp2 + 1], av.y, ws);
            }
        }
    }

#pragma unroll
    for (int p = 0; p < 32; p++) {
        float lo, hi;
        unpack2(acc[p], lo, hi);
        g_V[(size_t)(row0 + 2 * p + 0) * HID + j] = lo + bias;
        g_V[(size_t)(row0 + 2 * p + 1) * HID + j] = hi + bias;
    }
}

// ---------------------------------------------------------------------------
// Kernel 2: recurrence. 2-CTA cluster per chain (128 CTAs = 128 SMs).
// FINALIZER warps = local-k warps (kh == rank): no mbar wait, compute local
// partial early, finalize tanh, send h via st.async. REMOTE warps (kh != rank):
// wait the 2 wave-mbars, FMA over peer h (in 2 chunks, pipelined with
// arrival), STS partial, bar#1, loop. One full bar + one named finalizer bar.
// partial[] double-buffered by step parity (race-free without bar#2).
// ---------------------------------------------------------------------------
__global__ void __launch_bounds__(256, 1) __cluster_dims__(2, 1, 1)
rnn_kernel(const int* __restrict__ source, const float* __restrict__ W_hh,
           float* __restrict__ out)
{
    __shared__ float hs[2][256];
    __shared__ float partial[2][128];
    __shared__ int   srcs[SEQT];
    __shared__ __align__(8) unsigned long long mb[2][2];  // [buf][wave]

    const int t   = threadIdx.x;
    const int col = t & 127;
    const int kh  = t >> 7;
    const int b   = blockIdx.x >> 1;

    uint32_t rank;
    asm("mov.u32 %0, %%cluster_ctarank;" : "=r"(rank));

    const bool is_final = (kh == (int)rank);        // finalizer: local-k warps
    const int  jout     = (int)rank * 128 + col;    // finalizer's output column
    const int  k0       = is_final ? (int)rank * 128        // local k base
                                   : ((int)rank ^ 1) * 128; // peer k base
    // k0 == kh*128 in both cases; keep explicit for clarity.

    for (int i = t; i < SEQT; i += 256) srcs[i] = source[b * SEQT + i];

    // W_hh[k0..k0+127][jout] register-resident as 64 f32x2.
    // Finalizers cover (local k) x (own col); remote warps (peer k) x (own col).
    unsigned long long wreg[64];
#pragma unroll
    for (int i = 0; i < 64; i++)
        wreg[i] = pack2(W_hh[(size_t)(k0 + 2 * i + 0) * HID + jout],
                        W_hh[(size_t)(k0 + 2 * i + 1) * HID + jout]);

    hs[0][t] = 0.0f;
    hs[1][t] = 0.0f;
    if (t == 0) {
#pragma unroll
        for (int q = 0; q < 2; q++)
#pragma unroll
            for (int wv = 0; wv < 2; wv++) {
                mbar_init(smem_u32(&mb[q][wv]), 1);
                mbar_expect_tx(smem_u32(&mb[q][wv]), 256);  // 64 cols x 4B
            }
    }

    // Peer addresses for finalizer sends: peer hs slot + peer wave-mbar
    const int wave = (col >= 64) ? 0 : 1;  // hi cols (hi warps) send first -> wave0
    uint32_t peer_h[2], peer_mb[2], mb_l[2][2];
#pragma unroll
    for (int q = 0; q < 2; q++) {
        peer_h[q]  = mapa_peer(smem_u32(&hs[q][jout]), rank ^ 1u);
        peer_mb[q] = mapa_peer(smem_u32(&mb[q][wave]), rank ^ 1u);
        mb_l[q][0] = smem_u32(&mb[q][0]);
        mb_l[q][1] = smem_u32(&mb[q][1]);
    }

    __syncthreads();
    CLUSTER_SYNC();  // mbar init + expect_tx + zeroed hs visible cluster-wide

    float hval = 0.0f;
    const bool rearm = (!is_final) && (col == 0);  // one remote thread re-arms

#pragma unroll 1
    for (int step = 0; step < SEQT; step++) {
        const int cur = step & 1;
        const int nxt = cur ^ 1;
        const uint32_t par = ((uint32_t)(step - 1) >> 1) & 1u;

        if (is_final) {
            // ---- FINALIZER path: no mbar wait ----
            const float xv = g_V[(size_t)srcs[step] * HID + jout];

            const float* hp = &hs[cur][k0];  // local half: own-group writes
            unsigned long long a0 = 0, a1 = 0, a2 = 0, a3 = 0;
            unsigned long long b0 = 0, b1 = 0, b2 = 0, b3 = 0;
#pragma unroll
            for (int q = 0; q < 32; q += 4) {
                ulonglong2 h0 = *(const ulonglong2*)(hp + 4 * (q + 0));
                ulonglong2 h1 = *(const ulonglong2*)(hp + 4 * (q + 1));
                ulonglong2 h2 = *(const ulonglong2*)(hp + 4 * (q + 2));
                ulonglong2 h3 = *(const ulonglong2*)(hp + 4 * (q + 3));
                fma2(a0, h0.x, wreg[2 * q + 0]); fma2(b0, h0.y, wreg[2 * q + 1]);
                fma2(a1, h1.x, wreg[2 * q + 2]); fma2(b1, h1.y, wreg[2 * q + 3]);
                fma2(a2, h2.x, wreg[2 * q + 4]); fma2(b2, h2.y, wreg[2 * q + 5]);
                fma2(a3, h3.x, wreg[2 * q + 6]); fma2(b3, h3.y, wreg[2 * q + 7]);
            }
            unsigned long long s = add2(add2(add2(a0, a1), add2(a2, a3)),
                                        add2(add2(b0, b1), add2(b2, b3)));
            float lo, hi;
            unpack2(s, lo, hi);
            const float pr = lo + hi;

            __syncthreads();  // bar#1: remote partials of this step are in

            const float pre = xv + pr + partial[cur][col];
            const float e = __expf(2.0f * pre);
            hval = 1.0f - __fdividef(2.0f, e + 1.0f);

            hs[nxt][jout] = hval;                        // local copy (own group)
            st_async_f32(peer_h[nxt], hval, peer_mb[nxt]);  // peer copy + signal

            // Order finalizer h-writes vs next step's finalizer h-reads.
            asm volatile("bar.sync 1, 128;" ::: "memory");
        } else {
            // ---- REMOTE path: two-wave pipelined arrival ----
            unsigned long long a0 = 0, a1 = 0, a2 = 0, a3 = 0;
            unsigned long long b0 = 0, b1 = 0, b2 = 0, b3 = 0;

            // Wave 0: peer cols [64,128) -> h[k0+64 .. k0+128)
            if (step > 0) mbar_wait_parity(mb_l[cur][0], par);
            {
                const float* hp = &hs[cur][k0 + 64];
#pragma unroll
                for (int q = 0; q < 16; q += 4) {
                    ulonglong2 h0 = *(const ulonglong2*)(hp + 4 * (q + 0));
                    ulonglong2 h1 = *(const ulonglong2*)(hp + 4 * (q + 1));
                    ulonglong2 h2 = *(const ulonglong2*)(hp + 4 * (q + 2));
                    ulonglong2 h3 = *(const ulonglong2*)(hp + 4 * (q + 3));
                    fma2(a0, h0.x, wreg[32 + 2 * q + 0]); fma2(b0, h0.y, wreg[32 + 2 * q + 1]);
                    fma2(a1, h1.x, wreg[32 + 2 * q + 2]); fma2(b1, h1.y, wreg[32 + 2 * q + 3]);
                    fma2(a2, h2.x, wreg[32 + 2 * q + 4]); fma2(b2, h2.y, wreg[32 + 2 * q + 5]);
                    fma2(a3, h3.x, wreg[32 + 2 * q + 6]); fma2(b3, h3.y, wreg[32 + 2 * q + 7]);
                }
            }
            // Wave 1: peer cols [0,64) -> h[k0 .. k0+64)
            if (step > 0) mbar_wait_parity(mb_l[cur][1], par);
            {
                const float* hp = &hs[cur][k0];
#pragma unroll
                for (int q = 0; q < 16; q += 4) {
                    ulonglong2 h0 = *(const ulonglong2*)(hp + 4 * (q + 0));
                    ulonglong2 h1 = *(const ulonglong2*)(hp + 4 * (q + 1));
                    ulonglong2 h2 = *(const ulonglong2*)(hp + 4 * (q + 2));
                    ulonglong2 h3 = *(const ulonglong2*)(hp + 4 * (q + 3));
                    fma2(a0, h0.x, wreg[2 * q + 0]); fma2(b0, h0.y, wreg[2 * q + 1]);
                    fma2(a1, h1.x, wreg[2 * q + 2]); fma2(b1, h1.y, wreg[2 * q + 3]);
                    fma2(a2, h2.x, wreg[2 * q + 4]); fma2(b2, h2.y, wreg[2 * q + 5]);
                    fma2(a3, h3.x, wreg[2 * q + 6]); fma2(b3, h3.y, wreg[2 * q + 7]);
                }
            }

            // Re-arm this buffer's wave mbars for its next phase (2 steps out)
            if (rearm && step > 0) {
                mbar_expect_tx(mb_l[cur][0], 256);
                mbar_expect_tx(mb_l[cur][1], 256);
            }

            unsigned long long s = add2(add2(add2(a0, a1), add2(a2, a3)),
                                        add2(add2(b0, b1), add2(b2, b3)));
            float lo, hi;
            unpack2(s, lo, hi);
            partial[cur][col] = lo + hi;

            __syncthreads();  // bar#1: publish partials; then straight to next wait
        }
    }

    if (is_final) out[b * HID + jout] = hval;

    CLUSTER_SYNC();  // keep SMEM/mbar alive for in-flight final st.asyncs
}

// ---------------------------------------------------------------------------
extern "C" void kernel_launch(void* const* d_in, const int* in_sizes, int n_in,
                              void* d_out, int out_size)
{
    const int*   source    = (const int*)d_in[0];
    const float* embedding = (const float*)d_in[1];
    const float* W_ih      = (const float*)d_in[2];
    const float* W_hh      = (const float*)d_in[3];
    const float* b_ih      = (const float*)d_in[4];
    const float* b_hh      = (const float*)d_in[5];
    float* out = (float*)d_out;

    vocab_proj_kernel<<<VOCAB / 64, 256>>>(embedding, W_ih, b_ih, b_hh);
    rnn_kernel<<<BATCH * 2, 256>>>(source, W_hh, out);
}